// round 14
// baseline (speedup 1.0000x reference)
#include <cuda_runtime.h>
#include <cuda_bf16.h>
#include <cstdint>
#include <cstddef>

#define T_STEPS 2048
#define BATCH   32
#define DIM     512
#define HID     512
#define GATES   2048   // 4*HID

typedef unsigned long long ull;
typedef unsigned int u32;

// 512 MB scratch for gx = x @ w_ih^T + b_ih + b_hh
__device__ float g_gx[134217728];  // T_STEPS*BATCH*GATES

// bf16-split packed inputs: u32 = (hi bf16) | (lo bf16 << 16)
__device__ __align__(16) u32 g_xs[33554432];   // x   [65536, 512]
__device__ __align__(16) u32 g_ws[1048576];    // wih [2048, 512]

// double-buffered transposed hidden state h_T[buf][u][b]
__device__ __align__(16) float g_ht[2][HID * BATCH];

// per-chunk monotonic flags: chunk g = h rows [64g, 64g+64), produced by blocks 16g..16g+15
__device__ unsigned int g_cnt[8];

// ---------------- packed f32x2 helpers (Blackwell FFMA2 path) ----------------
__device__ __forceinline__ void ffma2(ull& d, ull a, ull b) {
    asm("fma.rn.f32x2 %0, %1, %2, %0;" : "+l"(d) : "l"(a), "l"(b));
}
__device__ __forceinline__ ull addf2(ull a, ull b) {
    ull r; asm("add.rn.f32x2 %0, %1, %2;" : "=l"(r) : "l"(a), "l"(b)); return r;
}
__device__ __forceinline__ ull pk2(float x, float y) {
    ull r; asm("mov.b64 %0, {%1, %2};" : "=l"(r) : "f"(x), "f"(y)); return r;
}
__device__ __forceinline__ float2 upk(ull v) {
    float2 r; asm("mov.b64 {%0, %1}, %2;" : "=f"(r.x), "=f"(r.y) : "l"(v)); return r;
}

// ---------------------------------------------------------------------------
// convert_split: pack x and w_ih into (hi|lo) bf16-split u32 arrays
// ---------------------------------------------------------------------------
__device__ __forceinline__ u32 pack_split(float x) {
    __nv_bfloat16 h = __float2bfloat16(x);
    float r = x - __bfloat162float(h);
    __nv_bfloat16 l = __float2bfloat16(r);
    return (u32)__bfloat16_as_ushort(h) | ((u32)__bfloat16_as_ushort(l) << 16);
}

__global__ void convert_split(const float* __restrict__ X, const float* __restrict__ W)
{
    const long long n4x = 33554432LL / 4;   // 8388608
    const long long n4w = 1048576LL / 4;    // 262144
    long long i = (long long)blockIdx.x * blockDim.x + threadIdx.x;
    const float4* src;
    uint4* dst;
    long long j;
    if (i < n4x)            { src = (const float4*)X; dst = (uint4*)g_xs; j = i; }
    else if (i < n4x + n4w) { src = (const float4*)W; dst = (uint4*)g_ws; j = i - n4x; }
    else return;
    float4 v = src[j];
    uint4 o;
    o.x = pack_split(v.x);
    o.y = pack_split(v.y);
    o.z = pack_split(v.z);
    o.w = pack_split(v.w);
    dst[j] = o;
}

// ---------------------------------------------------------------------------
// gemm_bf16x3: gx = x @ wih^T + bih + bhh via m16n8k16 bf16 MMA, 3-term split.
// ---------------------------------------------------------------------------
#define GP 9   // smem row pitch in u32 (= 18 bf16)

#define MMA_BF16(C, A0, A1, A2, A3, B0, B1)                                    \
    asm volatile(                                                              \
        "mma.sync.aligned.m16n8k16.row.col.f32.bf16.bf16.f32 "                 \
        "{%0,%1,%2,%3},{%4,%5,%6,%7},{%8,%9},{%0,%1,%2,%3};"                   \
        : "+f"((C)[0]), "+f"((C)[1]), "+f"((C)[2]), "+f"((C)[3])               \
        : "r"(A0), "r"(A1), "r"(A2), "r"(A3), "r"(B0), "r"(B1))

__global__ void __launch_bounds__(256, 2) gemm_bf16x3(
    const float* __restrict__ bih,
    const float* __restrict__ bhh)
{
    __shared__ u32 smem[2 * 4 * 128 * GP];

    const int tid = threadIdx.x;
    const int bm  = blockIdx.y * 128;
    const int bn  = blockIdx.x * 128;
    const int wid = tid >> 5;
    const int ln  = tid & 31;
    const int mw  = (wid >> 2) * 64;
    const int nw  = (wid & 3) * 32;
    const int lc  = ln & 3;
    const int lr4 = ln >> 2;

    const int lrow  = tid >> 1;
    const int lhalf = tid & 1;
    const u32* Ag = g_xs + (size_t)(bm + lrow) * 512 + lhalf * 8;
    const u32* Bg = g_ws + (size_t)(bn + lrow) * 512 + lhalf * 8;

    float acc[4][4][4];
#pragma unroll
    for (int mt = 0; mt < 4; mt++)
#pragma unroll
        for (int nt = 0; nt < 4; nt++)
#pragma unroll
            for (int q = 0; q < 4; q++) acc[mt][nt][q] = 0.f;

    float2 bias2[4];
#pragma unroll
    for (int nt = 0; nt < 4; nt++) {
        int c0 = bn + nw + nt * 8 + lc * 2;
        bias2[nt].x = bih[c0]     + bhh[c0];
        bias2[nt].y = bih[c0 + 1] + bhh[c0 + 1];
    }

    const int sts_base = lrow * GP + lhalf * 4;

    uint4 pa0 = *(const uint4*)(Ag);
    uint4 pa1 = *(const uint4*)(Ag + 4);
    uint4 pb0 = *(const uint4*)(Bg);
    uint4 pb1 = *(const uint4*)(Bg + 4);
    {
        u32* Ah = smem;               u32* Al = smem + 1152;
        u32* Bh = smem + 2304;        u32* Bl = smem + 3456;
        Ah[sts_base + 0] = __byte_perm(pa0.x, pa0.y, 0x5410);
        Ah[sts_base + 1] = __byte_perm(pa0.z, pa0.w, 0x5410);
        Ah[sts_base + 2] = __byte_perm(pa1.x, pa1.y, 0x5410);
        Ah[sts_base + 3] = __byte_perm(pa1.z, pa1.w, 0x5410);
        Al[sts_base + 0] = __byte_perm(pa0.x, pa0.y, 0x7632);
        Al[sts_base + 1] = __byte_perm(pa0.z, pa0.w, 0x7632);
        Al[sts_base + 2] = __byte_perm(pa1.x, pa1.y, 0x7632);
        Al[sts_base + 3] = __byte_perm(pa1.z, pa1.w, 0x7632);
        Bh[sts_base + 0] = __byte_perm(pb0.x, pb0.y, 0x5410);
        Bh[sts_base + 1] = __byte_perm(pb0.z, pb0.w, 0x5410);
        Bh[sts_base + 2] = __byte_perm(pb1.x, pb1.y, 0x5410);
        Bh[sts_base + 3] = __byte_perm(pb1.z, pb1.w, 0x5410);
        Bl[sts_base + 0] = __byte_perm(pb0.x, pb0.y, 0x7632);
        Bl[sts_base + 1] = __byte_perm(pb0.z, pb0.w, 0x7632);
        Bl[sts_base + 2] = __byte_perm(pb1.x, pb1.y, 0x7632);
        Bl[sts_base + 3] = __byte_perm(pb1.z, pb1.w, 0x7632);
    }
    __syncthreads();

    for (int s = 0; s < 32; s++) {
        if (s + 1 < 32) {
            pa0 = *(const uint4*)(Ag + (s + 1) * 16);
            pa1 = *(const uint4*)(Ag + (s + 1) * 16 + 4);
            pb0 = *(const uint4*)(Bg + (s + 1) * 16);
            pb1 = *(const uint4*)(Bg + (s + 1) * 16 + 4);
        }

        const u32* base = smem + (s & 1) * 4608;
        const u32* Ahi = base;
        const u32* Alo = base + 1152;
        const u32* Bhi = base + 2304;
        const u32* Blo = base + 3456;

        u32 bh[4][2], bl[4][2];
#pragma unroll
        for (int nt = 0; nt < 4; nt++) {
            int r = (nw + nt * 8 + lr4) * GP + lc;
            bh[nt][0] = Bhi[r];     bh[nt][1] = Bhi[r + 4];
            bl[nt][0] = Blo[r];     bl[nt][1] = Blo[r + 4];
        }

#pragma unroll
        for (int mt = 0; mt < 4; mt++) {
            int r0 = (mw + mt * 16 + lr4) * GP + lc;
            int r1 = r0 + 8 * GP;
            u32 ah0 = Ahi[r0], ah1 = Ahi[r1], ah2 = Ahi[r0 + 4], ah3 = Ahi[r1 + 4];
            u32 al0 = Alo[r0], al1 = Alo[r1], al2 = Alo[r0 + 4], al3 = Alo[r1 + 4];
#pragma unroll
            for (int nt = 0; nt < 4; nt++) {
                MMA_BF16(acc[mt][nt], ah0, ah1, ah2, ah3, bh[nt][0], bh[nt][1]);
                MMA_BF16(acc[mt][nt], ah0, ah1, ah2, ah3, bl[nt][0], bl[nt][1]);
                MMA_BF16(acc[mt][nt], al0, al1, al2, al3, bh[nt][0], bh[nt][1]);
            }
        }

        if (s + 1 < 32) {
            u32* nb = smem + ((s + 1) & 1) * 4608;
            u32* Ah = nb;          u32* Al = nb + 1152;
            u32* Bh = nb + 2304;   u32* Bl = nb + 3456;
            Ah[sts_base + 0] = __byte_perm(pa0.x, pa0.y, 0x5410);
            Ah[sts_base + 1] = __byte_perm(pa0.z, pa0.w, 0x5410);
            Ah[sts_base + 2] = __byte_perm(pa1.x, pa1.y, 0x5410);
            Ah[sts_base + 3] = __byte_perm(pa1.z, pa1.w, 0x5410);
            Al[sts_base + 0] = __byte_perm(pa0.x, pa0.y, 0x7632);
            Al[sts_base + 1] = __byte_perm(pa0.z, pa0.w, 0x7632);
            Al[sts_base + 2] = __byte_perm(pa1.x, pa1.y, 0x7632);
            Al[sts_base + 3] = __byte_perm(pa1.z, pa1.w, 0x7632);
            Bh[sts_base + 0] = __byte_perm(pb0.x, pb0.y, 0x5410);
            Bh[sts_base + 1] = __byte_perm(pb0.z, pb0.w, 0x5410);
            Bh[sts_base + 2] = __byte_perm(pb1.x, pb1.y, 0x5410);
            Bh[sts_base + 3] = __byte_perm(pb1.z, pb1.w, 0x5410);
            Bl[sts_base + 0] = __byte_perm(pb0.x, pb0.y, 0x7632);
            Bl[sts_base + 1] = __byte_perm(pb0.z, pb0.w, 0x7632);
            Bl[sts_base + 2] = __byte_perm(pb1.x, pb1.y, 0x7632);
            Bl[sts_base + 3] = __byte_perm(pb1.z, pb1.w, 0x7632);
            __syncthreads();
        }
    }

#pragma unroll
    for (int mt = 0; mt < 4; mt++) {
        int grow = bm + mw + mt * 16 + lr4;
#pragma unroll
        for (int nt = 0; nt < 4; nt++) {
            int gcol = bn + nw + nt * 8 + lc * 2;
            float2 v0 = { acc[mt][nt][0] + bias2[nt].x,
                          acc[mt][nt][1] + bias2[nt].y };
            float2 v1 = { acc[mt][nt][2] + bias2[nt].x,
                          acc[mt][nt][3] + bias2[nt].y };
            *(float2*)&g_gx[(size_t)grow * GATES + gcol]       = v0;
            *(float2*)&g_gx[(size_t)(grow + 8) * GATES + gcol] = v1;
        }
    }
}

// ---------------------------------------------------------------------------
// init: reset chunk flags + transpose h0 into g_ht[1][u][b]  (step 0 reads buf 1)
// ---------------------------------------------------------------------------
__global__ void init_rec(const float* __restrict__ h0)
{
    int i = blockIdx.x * 256 + threadIdx.x;   // 0..16383
    if (i < 8) g_cnt[i] = 0u;
    int b = i >> 9;
    int u = i & 511;
    g_ht[1][u * BATCH + b] = h0[i];
}

// ---------------------------------------------------------------------------
// Kernel 2: persistent recurrence — R13 core, pack-free FFMA2:
//   acc pairs = (batch-pair), multiplier w duplicated in smem (WT2).
//   h loads arrive pre-packed (adjacent batches). Zero MOV packs in the loop.
// ---------------------------------------------------------------------------
#define RBLK 128
#define RTHR 256
// smem floats: WT2[512*16 ull]=16384 | RED[8*576]=4608 | CS[128]
#define SMEM_FLOATS (16384 + 4608 + 128)

__global__ void __launch_bounds__(RTHR, 1) lstm_rec(
    const float* __restrict__ c0,
    const float* __restrict__ whh,
    float* __restrict__ out, float* __restrict__ hn, float* __restrict__ cn)
{
    extern __shared__ float sm[];
    ull*   WT2 = (ull*)sm;        // [k:512][c:16] each = (w,w) duplicated
    float* RED = sm + 16384;      // [ks:8][b*18 + c]
    float* CS  = RED + 4608;      // [bb*4+uu]

    const int tid = threadIdx.x;
    const int u0  = blockIdx.x * 4;
    const int my_chunk = blockIdx.x >> 4;     // chunk this block produces

    // load w_hh slice duplicated: col c = uu*4+gate <-> row gate*512 + u0+uu
    for (int idx = tid; idx < 8192; idx += RTHR) {
        int c    = idx & 15;
        int k    = idx >> 4;
        int uu   = c >> 2;
        int gate = c & 3;
        float w  = whh[(size_t)(gate * HID + u0 + uu) * HID + k];
        WT2[idx] = pk2(w, w);
    }
    if (tid < 128) {
        int bb = tid >> 2, uu = tid & 3;
        CS[bb * 4 + uu] = c0[bb * HID + u0 + uu];
    }
    __syncthreads();

    const int ks  = tid >> 5;          // 0..7  (also = chunk this warp consumes)
    const int ln  = tid & 31;
    const int bq  = ln & 7;            // batches 4bq..4bq+3
    const int cq  = ln >> 3;           // cols 4cq..4cq+3
    const int ebb = tid & 31;          // epilogue batch
    const int euu = tid >> 5;          // epilogue unit (tid<128)

    // gx prefetch for t=0
    float gxv[4];
    if (tid < 128) {
        const size_t base = (size_t)ebb * GATES;
#pragma unroll
        for (int g = 0; g < 4; g++)
            gxv[g] = g_gx[base + g * HID + (u0 + euu)];
    }

    for (int t = 0; t < T_STEPS; t++) {
        const int rb = (t & 1) ^ 1;    // read buffer (h_{t-1})
        const int wb = t & 1;          // write buffer (h_t)

        // per-warp chunk wait: h_{t-1} rows 64ks.. ready when g_cnt[ks] >= 16*t
        if (t > 0) {
            if (ln == 0) {
                const unsigned tgt = 16u * (unsigned)t;
                unsigned v;
                do {
                    asm volatile("ld.acquire.gpu.global.u32 %0, [%1];"
                                 : "=r"(v) : "l"(&g_cnt[ks]) : "memory");
                } while (v < tgt);
            }
            __syncwarp();
        }

        // pack-free GEMM: acc2[p][c] += (h pair p) * (w dup c)
        ull acc2[2][4];
#pragma unroll
        for (int p = 0; p < 2; p++)
#pragma unroll
            for (int c = 0; c < 4; c++) acc2[p][c] = 0ull;

        const longlong2* hp = (const longlong2*)(g_ht[rb] + (ks * 64) * BATCH + bq * 4);
        const ull*       wp = WT2 + (ks * 64) * 16 + cq * 4;
#pragma unroll 16
        for (int k = 0; k < 64; k++) {
            longlong2 hq = __ldcg(hp); hp += 8;         // +32 floats (one row)
            ull h01 = (ull)hq.x;                        // (h_b0, h_b1) pre-packed
            ull h23 = (ull)hq.y;                        // (h_b2, h_b3)
            ulonglong2 w01 = *(const ulonglong2*)wp;
            ulonglong2 w23 = *(const ulonglong2*)(wp + 2);
            wp += 16;
            ffma2(acc2[0][0], h01, w01.x);
            ffma2(acc2[0][1], h01, w01.y);
            ffma2(acc2[0][2], h01, w23.x);
            ffma2(acc2[0][3], h01, w23.y);
            ffma2(acc2[1][0], h23, w01.x);
            ffma2(acc2[1][1], h23, w01.y);
            ffma2(acc2[1][2], h23, w23.x);
            ffma2(acc2[1][3], h23, w23.y);
        }
        // write partials (scalar halves) into the SAME RED[b][c] layout as R13
        {
            float* rbuf = RED + ks * 576;
#pragma unroll
            for (int p = 0; p < 2; p++)
#pragma unroll
                for (int c = 0; c < 4; c++) {
                    float2 v = upk(acc2[p][c]);
                    rbuf[(4 * bq + 2 * p)     * 18 + 4 * cq + c] = v.x;
                    rbuf[(4 * bq + 2 * p + 1) * 18 + 4 * cq + c] = v.y;
                }
        }
        __syncthreads();   // RED ready; warps 4..7 fall through to next poll

        if (tid < 128) {
            const ull* q = (const ull*)(RED + ebb * 18 + euu * 4);
            ull s01 = 0ull, s23 = 0ull;
#pragma unroll
            for (int kq = 0; kq < 8; kq++) {
                s01 = addf2(s01, q[0]);
                s23 = addf2(s23, q[1]);
                q += 288;   // 576 floats
            }
            float2 p01 = upk(s01);
            float2 p23 = upk(s23);
            float iv = p01.x + gxv[0];
            float fv = p01.y + gxv[1];
            float gv = p23.x + gxv[2];
            float ov = p23.y + gxv[3];
            float it = 1.f / (1.f + __expf(-iv));
            float ft = 1.f / (1.f + __expf(-fv));
            float gt = tanhf(gv);
            float ot = 1.f / (1.f + __expf(-ov));
            float cc  = CS[ebb * 4 + euu];
            float cnv = ft * cc + it * gt;
            CS[ebb * 4 + euu] = cnv;
            float hv = ot * tanhf(cnv);

            // publish h_t, then release ASAP (epi-warp barrier only)
            g_ht[wb][(u0 + euu) * BATCH + ebb] = hv;
            asm volatile("bar.sync 1, 128;" ::: "memory");
            if (tid == 0 && t < T_STEPS - 1) {
                asm volatile("red.release.gpu.global.add.u32 [%0], 1;"
                             :: "l"(&g_cnt[my_chunk]) : "memory");
            }

            // off-critical-path work
            out[(size_t)t * BATCH * HID + ebb * HID + (u0 + euu)] = hv;
            if (t + 1 < T_STEPS) {
                const size_t base = ((size_t)(t + 1) * BATCH + ebb) * GATES;
#pragma unroll
                for (int g = 0; g < 4; g++)
                    gxv[g] = g_gx[base + g * HID + (u0 + euu)];
            } else {
                hn[ebb * HID + (u0 + euu)] = hv;
                cn[ebb * HID + (u0 + euu)] = cnv;
            }
        }
        // warps 4..7 loop straight to the next chunk wait (RED WAR safe via wait)
    }
}

// ---------------------------------------------------------------------------
extern "C" void kernel_launch(void* const* d_in, const int* in_sizes, int n_in,
                              void* d_out, int out_size)
{
    const float* x   = (const float*)d_in[0];
    const float* h0  = (const float*)d_in[1];
    const float* c0  = (const float*)d_in[2];
    const float* wih = (const float*)d_in[3];
    const float* bih = (const float*)d_in[4];
    const float* whh = (const float*)d_in[5];
    const float* bhh = (const float*)d_in[6];

    float* out = (float*)d_out;
    float* hn  = out + (size_t)T_STEPS * BATCH * HID;
    float* cn  = hn + BATCH * HID;

    init_rec<<<64, 256>>>(h0);
    convert_split<<<33792, 256>>>(x, wih);
    gemm_bf16x3<<<dim3(GATES / 128, (T_STEPS * BATCH) / 128), 256>>>(bih, bhh);

    const size_t shmem = SMEM_FLOATS * sizeof(float);
    cudaFuncSetAttribute(lstm_rec, cudaFuncAttributeMaxDynamicSharedMemorySize, (int)shmem);
    lstm_rec<<<RBLK, RTHR, shmem>>>(c0, whh, out, hn, cn);
}

// round 15
// speedup vs baseline: 1.1204x; 1.1204x over previous
#include <cuda_runtime.h>
#include <cuda_bf16.h>
#include <cstdint>
#include <cstddef>

#define T_STEPS 2048
#define BATCH   32
#define DIM     512
#define HID     512
#define GATES   2048   // 4*HID

typedef unsigned long long ull;
typedef unsigned int u32;

// 512 MB scratch for gx = x @ w_ih^T + b_ih + b_hh
__device__ float g_gx[134217728];   // [t*32+b][g*512+u]
// rec-friendly transposed copy: [t][ublk:128][b:32][uu:4][g:4]
__device__ float g_gxT[134217728];

// bf16-split packed inputs: u32 = (hi bf16) | (lo bf16 << 16)
__device__ __align__(16) u32 g_xs[33554432];   // x   [65536, 512]
__device__ __align__(16) u32 g_ws[1048576];    // wih [2048, 512]

// double-buffered transposed hidden state h_T[buf][u][b]
__device__ __align__(16) float g_ht[2][HID * BATCH];

// per-chunk monotonic flags: chunk g = h rows [64g, 64g+64), produced by blocks 16g..16g+15
__device__ unsigned int g_cnt[8];

// ---------------- packed f32x2 helpers (Blackwell FFMA2 path) ----------------
__device__ __forceinline__ void ffma2(ull& d, ull a, ull b) {
    asm("fma.rn.f32x2 %0, %1, %2, %0;" : "+l"(d) : "l"(a), "l"(b));
}
__device__ __forceinline__ ull addf2(ull a, ull b) {
    ull r; asm("add.rn.f32x2 %0, %1, %2;" : "=l"(r) : "l"(a), "l"(b)); return r;
}
__device__ __forceinline__ ull pk2(float x, float y) {
    ull r; asm("mov.b64 %0, {%1, %2};" : "=l"(r) : "f"(x), "f"(y)); return r;
}
__device__ __forceinline__ float2 upk(ull v) {
    float2 r; asm("mov.b64 {%0, %1}, %2;" : "=f"(r.x), "=f"(r.y) : "l"(v)); return r;
}

// ---------------------------------------------------------------------------
// convert_split: pack x and w_ih into (hi|lo) bf16-split u32 arrays
// ---------------------------------------------------------------------------
__device__ __forceinline__ u32 pack_split(float x) {
    __nv_bfloat16 h = __float2bfloat16(x);
    float r = x - __bfloat162float(h);
    __nv_bfloat16 l = __float2bfloat16(r);
    return (u32)__bfloat16_as_ushort(h) | ((u32)__bfloat16_as_ushort(l) << 16);
}

__global__ void convert_split(const float* __restrict__ X, const float* __restrict__ W)
{
    const long long n4x = 33554432LL / 4;
    const long long n4w = 1048576LL / 4;
    long long i = (long long)blockIdx.x * blockDim.x + threadIdx.x;
    const float4* src;
    uint4* dst;
    long long j;
    if (i < n4x)            { src = (const float4*)X; dst = (uint4*)g_xs; j = i; }
    else if (i < n4x + n4w) { src = (const float4*)W; dst = (uint4*)g_ws; j = i - n4x; }
    else return;
    float4 v = src[j];
    uint4 o;
    o.x = pack_split(v.x);
    o.y = pack_split(v.y);
    o.z = pack_split(v.z);
    o.w = pack_split(v.w);
    dst[j] = o;
}

// ---------------------------------------------------------------------------
// gemm_bf16x3: gx = x @ wih^T + bih + bhh via m16n8k16 bf16 MMA, 3-term split.
// ---------------------------------------------------------------------------
#define GP 9   // smem row pitch in u32

#define MMA_BF16(C, A0, A1, A2, A3, B0, B1)                                    \
    asm volatile(                                                              \
        "mma.sync.aligned.m16n8k16.row.col.f32.bf16.bf16.f32 "                 \
        "{%0,%1,%2,%3},{%4,%5,%6,%7},{%8,%9},{%0,%1,%2,%3};"                   \
        : "+f"((C)[0]), "+f"((C)[1]), "+f"((C)[2]), "+f"((C)[3])               \
        : "r"(A0), "r"(A1), "r"(A2), "r"(A3), "r"(B0), "r"(B1))

__global__ void __launch_bounds__(256, 2) gemm_bf16x3(
    const float* __restrict__ bih,
    const float* __restrict__ bhh)
{
    __shared__ u32 smem[2 * 4 * 128 * GP];

    const int tid = threadIdx.x;
    const int bm  = blockIdx.y * 128;
    const int bn  = blockIdx.x * 128;
    const int wid = tid >> 5;
    const int ln  = tid & 31;
    const int mw  = (wid >> 2) * 64;
    const int nw  = (wid & 3) * 32;
    const int lc  = ln & 3;
    const int lr4 = ln >> 2;

    const int lrow  = tid >> 1;
    const int lhalf = tid & 1;
    const u32* Ag = g_xs + (size_t)(bm + lrow) * 512 + lhalf * 8;
    const u32* Bg = g_ws + (size_t)(bn + lrow) * 512 + lhalf * 8;

    float acc[4][4][4];
#pragma unroll
    for (int mt = 0; mt < 4; mt++)
#pragma unroll
        for (int nt = 0; nt < 4; nt++)
#pragma unroll
            for (int q = 0; q < 4; q++) acc[mt][nt][q] = 0.f;

    float2 bias2[4];
#pragma unroll
    for (int nt = 0; nt < 4; nt++) {
        int c0 = bn + nw + nt * 8 + lc * 2;
        bias2[nt].x = bih[c0]     + bhh[c0];
        bias2[nt].y = bih[c0 + 1] + bhh[c0 + 1];
    }

    const int sts_base = lrow * GP + lhalf * 4;

    uint4 pa0 = *(const uint4*)(Ag);
    uint4 pa1 = *(const uint4*)(Ag + 4);
    uint4 pb0 = *(const uint4*)(Bg);
    uint4 pb1 = *(const uint4*)(Bg + 4);
    {
        u32* Ah = smem;               u32* Al = smem + 1152;
        u32* Bh = smem + 2304;        u32* Bl = smem + 3456;
        Ah[sts_base + 0] = __byte_perm(pa0.x, pa0.y, 0x5410);
        Ah[sts_base + 1] = __byte_perm(pa0.z, pa0.w, 0x5410);
        Ah[sts_base + 2] = __byte_perm(pa1.x, pa1.y, 0x5410);
        Ah[sts_base + 3] = __byte_perm(pa1.z, pa1.w, 0x5410);
        Al[sts_base + 0] = __byte_perm(pa0.x, pa0.y, 0x7632);
        Al[sts_base + 1] = __byte_perm(pa0.z, pa0.w, 0x7632);
        Al[sts_base + 2] = __byte_perm(pa1.x, pa1.y, 0x7632);
        Al[sts_base + 3] = __byte_perm(pa1.z, pa1.w, 0x7632);
        Bh[sts_base + 0] = __byte_perm(pb0.x, pb0.y, 0x5410);
        Bh[sts_base + 1] = __byte_perm(pb0.z, pb0.w, 0x5410);
        Bh[sts_base + 2] = __byte_perm(pb1.x, pb1.y, 0x5410);
        Bh[sts_base + 3] = __byte_perm(pb1.z, pb1.w, 0x5410);
        Bl[sts_base + 0] = __byte_perm(pb0.x, pb0.y, 0x7632);
        Bl[sts_base + 1] = __byte_perm(pb0.z, pb0.w, 0x7632);
        Bl[sts_base + 2] = __byte_perm(pb1.x, pb1.y, 0x7632);
        Bl[sts_base + 3] = __byte_perm(pb1.z, pb1.w, 0x7632);
    }
    __syncthreads();

    for (int s = 0; s < 32; s++) {
        if (s + 1 < 32) {
            pa0 = *(const uint4*)(Ag + (s + 1) * 16);
            pa1 = *(const uint4*)(Ag + (s + 1) * 16 + 4);
            pb0 = *(const uint4*)(Bg + (s + 1) * 16);
            pb1 = *(const uint4*)(Bg + (s + 1) * 16 + 4);
        }

        const u32* base = smem + (s & 1) * 4608;
        const u32* Ahi = base;
        const u32* Alo = base + 1152;
        const u32* Bhi = base + 2304;
        const u32* Blo = base + 3456;

        u32 bh[4][2], bl[4][2];
#pragma unroll
        for (int nt = 0; nt < 4; nt++) {
            int r = (nw + nt * 8 + lr4) * GP + lc;
            bh[nt][0] = Bhi[r];     bh[nt][1] = Bhi[r + 4];
            bl[nt][0] = Blo[r];     bl[nt][1] = Blo[r + 4];
        }

#pragma unroll
        for (int mt = 0; mt < 4; mt++) {
            int r0 = (mw + mt * 16 + lr4) * GP + lc;
            int r1 = r0 + 8 * GP;
            u32 ah0 = Ahi[r0], ah1 = Ahi[r1], ah2 = Ahi[r0 + 4], ah3 = Ahi[r1 + 4];
            u32 al0 = Alo[r0], al1 = Alo[r1], al2 = Alo[r0 + 4], al3 = Alo[r1 + 4];
#pragma unroll
            for (int nt = 0; nt < 4; nt++) {
                MMA_BF16(acc[mt][nt], ah0, ah1, ah2, ah3, bh[nt][0], bh[nt][1]);
                MMA_BF16(acc[mt][nt], ah0, ah1, ah2, ah3, bl[nt][0], bl[nt][1]);
                MMA_BF16(acc[mt][nt], al0, al1, al2, al3, bh[nt][0], bh[nt][1]);
            }
        }

        if (s + 1 < 32) {
            u32* nb = smem + ((s + 1) & 1) * 4608;
            u32* Ah = nb;          u32* Al = nb + 1152;
            u32* Bh = nb + 2304;   u32* Bl = nb + 3456;
            Ah[sts_base + 0] = __byte_perm(pa0.x, pa0.y, 0x5410);
            Ah[sts_base + 1] = __byte_perm(pa0.z, pa0.w, 0x5410);
            Ah[sts_base + 2] = __byte_perm(pa1.x, pa1.y, 0x5410);
            Ah[sts_base + 3] = __byte_perm(pa1.z, pa1.w, 0x5410);
            Al[sts_base + 0] = __byte_perm(pa0.x, pa0.y, 0x7632);
            Al[sts_base + 1] = __byte_perm(pa0.z, pa0.w, 0x7632);
            Al[sts_base + 2] = __byte_perm(pa1.x, pa1.y, 0x7632);
            Al[sts_base + 3] = __byte_perm(pa1.z, pa1.w, 0x7632);
            Bh[sts_base + 0] = __byte_perm(pb0.x, pb0.y, 0x5410);
            Bh[sts_base + 1] = __byte_perm(pb0.z, pb0.w, 0x5410);
            Bh[sts_base + 2] = __byte_perm(pb1.x, pb1.y, 0x5410);
            Bh[sts_base + 3] = __byte_perm(pb1.z, pb1.w, 0x5410);
            Bl[sts_base + 0] = __byte_perm(pb0.x, pb0.y, 0x7632);
            Bl[sts_base + 1] = __byte_perm(pb0.z, pb0.w, 0x7632);
            Bl[sts_base + 2] = __byte_perm(pb1.x, pb1.y, 0x7632);
            Bl[sts_base + 3] = __byte_perm(pb1.z, pb1.w, 0x7632);
            __syncthreads();
        }
    }

#pragma unroll
    for (int mt = 0; mt < 4; mt++) {
        int grow = bm + mw + mt * 16 + lr4;
#pragma unroll
        for (int nt = 0; nt < 4; nt++) {
            int gcol = bn + nw + nt * 8 + lc * 2;
            float2 v0 = { acc[mt][nt][0] + bias2[nt].x,
                          acc[mt][nt][1] + bias2[nt].y };
            float2 v1 = { acc[mt][nt][2] + bias2[nt].x,
                          acc[mt][nt][3] + bias2[nt].y };
            *(float2*)&g_gx[(size_t)grow * GATES + gcol]       = v0;
            *(float2*)&g_gx[(size_t)(grow + 8) * GATES + gcol] = v1;
        }
    }
}

// ---------------------------------------------------------------------------
// transpose_gx: g_gx[t*32+b][g*512+u] -> g_gxT[t][ublk][b][uu][g]
//   Each thread emits one float4 (g=0..3). Writes fully coalesced.
// ---------------------------------------------------------------------------
__global__ void transpose_gx()
{
    long long i = (long long)blockIdx.x * 256 + threadIdx.x;   // 0 .. 33554431
    int uu   = (int)(i & 3);
    int b    = (int)((i >> 2) & 31);
    int ublk = (int)((i >> 7) & 127);
    int t    = (int)(i >> 14);
    const size_t rbase = ((size_t)t * 32 + b) * GATES + ublk * 4 + uu;
    float4 v;
    v.x = g_gx[rbase];
    v.y = g_gx[rbase + 512];
    v.z = g_gx[rbase + 1024];
    v.w = g_gx[rbase + 1536];
    *(float4*)&g_gxT[(size_t)i * 4] = v;
}

// ---------------------------------------------------------------------------
// init: reset chunk flags + transpose h0 into g_ht[1][u][b]  (step 0 reads buf 1)
// ---------------------------------------------------------------------------
__global__ void init_rec(const float* __restrict__ h0)
{
    int i = blockIdx.x * 256 + threadIdx.x;   // 0..16383
    if (i < 8) g_cnt[i] = 0u;
    int b = i >> 9;
    int u = i & 511;
    g_ht[1][u * BATCH + b] = h0[i];
}

// ---------------------------------------------------------------------------
// Kernel 2: persistent recurrence — R13 core + coalesced gx prefetch (gxT,
//   one float4/thread) + out stores bounced through smem (32x STG.128).
// ---------------------------------------------------------------------------
#define RBLK 128
#define RTHR 256
// smem floats: WT[512*16]=8192 | RED[8*576]=4608 | CS[128] | HOUT[128]
#define SMEM_FLOATS (8192 + 4608 + 128 + 128)

__global__ void __launch_bounds__(RTHR, 1) lstm_rec(
    const float* __restrict__ c0,
    const float* __restrict__ whh,
    float* __restrict__ out, float* __restrict__ hn, float* __restrict__ cn)
{
    extern __shared__ float sm[];
    float* WT   = sm;             // [k:512][c:16]
    float* RED  = sm + 8192;      // [ks:8][b*18 + c]
    float* CS   = RED + 4608;     // [bb*4+uu]
    float* HOUT = CS + 128;       // [b:32][uu:4]

    const int tid = threadIdx.x;
    const int u0  = blockIdx.x * 4;
    const int my_chunk = blockIdx.x >> 4;

    // load w_hh slice: local col c = uu*4+gate <-> global row gate*512 + u0+uu
    for (int idx = tid; idx < 8192; idx += RTHR) {
        int c    = idx & 15;
        int k    = idx >> 4;
        int uu   = c >> 2;
        int gate = c & 3;
        int grow = gate * HID + u0 + uu;
        WT[idx] = whh[(size_t)grow * HID + k];
    }
    if (tid < 128) {
        int bb = tid >> 2, uu = tid & 3;
        CS[bb * 4 + uu] = c0[bb * HID + u0 + uu];
    }
    __syncthreads();

    const int ks  = tid >> 5;          // 0..7  (also = chunk this warp consumes)
    const int ln  = tid & 31;
    const int bq  = ln & 7;            // batches 4bq..4bq+3
    const int cq  = ln >> 3;           // cols 4cq..4cq+3
    const int ebb = tid & 31;          // epilogue batch
    const int euu = tid >> 5;          // epilogue unit (tid<128)

    // gx prefetch for t=0 (coalesced float4 from gxT)
    float4 gxv;
    if (tid < 128) {
        gxv = *(const float4*)&g_gxT[((size_t)0 * 128 + blockIdx.x) * 512
                                     + ebb * 16 + euu * 4];
    }

    for (int t = 0; t < T_STEPS; t++) {
        const int rb = (t & 1) ^ 1;    // read buffer (h_{t-1})
        const int wb = t & 1;          // write buffer (h_t)

        // per-warp chunk wait: h_{t-1} rows 64ks.. ready when g_cnt[ks] >= 16*t
        if (t > 0) {
            if (ln == 0) {
                const unsigned tgt = 16u * (unsigned)t;
                unsigned v;
                do {
                    asm volatile("ld.acquire.gpu.global.u32 %0, [%1];"
                                 : "=r"(v) : "l"(&g_cnt[ks]) : "memory");
                } while (v < tgt);
            }
            __syncwarp();
        }

        // 4x4 microtile GEMM; h rows direct from L2 (fresh via ldcg)
        ull acc2[4][2];
#pragma unroll
        for (int i = 0; i < 4; i++) { acc2[i][0] = 0ull; acc2[i][1] = 0ull; }

        const float4* hp = (const float4*)(g_ht[rb] + (ks * 64) * BATCH + bq * 4);
        const float*  wp = WT + (ks * 64) * 16 + cq * 4;
#pragma unroll 16
        for (int k = 0; k < 64; k++) {
            float4 hv = __ldcg(hp); hp += 8;           // +32 floats (one row)
            ulonglong2 wq = *(const ulonglong2*)wp; wp += 16;
            ull h0d = pk2(hv.x, hv.x);
            ull h1d = pk2(hv.y, hv.y);
            ull h2d = pk2(hv.z, hv.z);
            ull h3d = pk2(hv.w, hv.w);
            ffma2(acc2[0][0], h0d, wq.x); ffma2(acc2[0][1], h0d, wq.y);
            ffma2(acc2[1][0], h1d, wq.x); ffma2(acc2[1][1], h1d, wq.y);
            ffma2(acc2[2][0], h2d, wq.x); ffma2(acc2[2][1], h2d, wq.y);
            ffma2(acc2[3][0], h3d, wq.x); ffma2(acc2[3][1], h3d, wq.y);
        }
        // write partials: RED[ks][b:32][c:16 pad 18]
        {
            float* rbuf = RED + ks * 576;
#pragma unroll
            for (int bb = 0; bb < 4; bb++) {
                ull* rp = (ull*)(rbuf + (4 * bq + bb) * 18 + 4 * cq);
                rp[0] = acc2[bb][0];
                rp[1] = acc2[bb][1];
            }
        }
        __syncthreads();   // RED ready; warps 4..7 fall through to next poll

        if (tid < 128) {
            const ull* q = (const ull*)(RED + ebb * 18 + euu * 4);
            ull s01 = 0ull, s23 = 0ull;
#pragma unroll
            for (int kq = 0; kq < 8; kq++) {
                s01 = addf2(s01, q[0]);
                s23 = addf2(s23, q[1]);
                q += 288;   // 576 floats
            }
            float2 p01 = upk(s01);
            float2 p23 = upk(s23);
            float iv = p01.x + gxv.x;
            float fv = p01.y + gxv.y;
            float gv = p23.x + gxv.z;
            float ov = p23.y + gxv.w;
            float it = 1.f / (1.f + __expf(-iv));
            float ft = 1.f / (1.f + __expf(-fv));
            float gt = tanhf(gv);
            float ot = 1.f / (1.f + __expf(-ov));
            float cc  = CS[ebb * 4 + euu];
            float cnv = ft * cc + it * gt;
            CS[ebb * 4 + euu] = cnv;
            float hv = ot * tanhf(cnv);

            // publish h_t + stage for coalesced out-store, then release ASAP
            g_ht[wb][(u0 + euu) * BATCH + ebb] = hv;
            HOUT[ebb * 4 + euu] = hv;
            asm volatile("bar.sync 1, 128;" ::: "memory");
            if (tid == 0 && t < T_STEPS - 1) {
                asm volatile("red.release.gpu.global.add.u32 [%0], 1;"
                             :: "l"(&g_cnt[my_chunk]) : "memory");
            }

            // off-critical-path: coalesced out store (32 x STG.128)
            if (tid < 32)
                *(float4*)&out[(size_t)t * BATCH * HID + tid * HID + u0] =
                    *(const float4*)&HOUT[tid * 4];

            // coalesced gx prefetch for t+1 (one float4/thread)
            if (t + 1 < T_STEPS) {
                gxv = *(const float4*)&g_gxT[((size_t)(t + 1) * 128 + blockIdx.x) * 512
                                             + ebb * 16 + euu * 4];
            } else {
                hn[ebb * HID + (u0 + euu)] = hv;
                cn[ebb * HID + (u0 + euu)] = cnv;
            }
        }
        // warps 4..7 loop straight to the next chunk wait (RED WAR safe via wait)
    }
}

// ---------------------------------------------------------------------------
extern "C" void kernel_launch(void* const* d_in, const int* in_sizes, int n_in,
                              void* d_out, int out_size)
{
    const float* x   = (const float*)d_in[0];
    const float* h0  = (const float*)d_in[1];
    const float* c0  = (const float*)d_in[2];
    const float* wih = (const float*)d_in[3];
    const float* bih = (const float*)d_in[4];
    const float* whh = (const float*)d_in[5];
    const float* bhh = (const float*)d_in[6];

    float* out = (float*)d_out;
    float* hn  = out + (size_t)T_STEPS * BATCH * HID;
    float* cn  = hn + BATCH * HID;

    init_rec<<<64, 256>>>(h0);
    convert_split<<<33792, 256>>>(x, wih);
    gemm_bf16x3<<<dim3(GATES / 128, (T_STEPS * BATCH) / 128), 256>>>(bih, bhh);
    transpose_gx<<<131072, 256>>>();

    const size_t shmem = SMEM_FLOATS * sizeof(float);
    cudaFuncSetAttribute(lstm_rec, cudaFuncAttributeMaxDynamicSharedMemorySize, (int)shmem);
    lstm_rec<<<RBLK, RTHR, shmem>>>(c0, whh, out, hn, cn);
}

// round 16
// speedup vs baseline: 1.1220x; 1.0014x over previous
#include <cuda_runtime.h>
#include <cuda_bf16.h>
#include <cstdint>
#include <cstddef>

#define T_STEPS 2048
#define BATCH   32
#define DIM     512
#define HID     512
#define GATES   2048   // 4*HID

typedef unsigned long long ull;
typedef unsigned int u32;

// gx in rec-friendly layout: [t][g:4][ublk:128][uu:4][b:32]
__device__ float g_gxT[134217728];

// bf16-split packed inputs: u32 = (hi bf16) | (lo bf16 << 16)
__device__ __align__(16) u32 g_xs[33554432];   // x   [65536, 512]
__device__ __align__(16) u32 g_ws[1048576];    // wih [2048, 512]

// double-buffered transposed hidden state h_T[buf][u][b]
__device__ __align__(16) float g_ht[2][HID * BATCH];

// per-chunk monotonic flags: chunk g = h rows [64g, 64g+64), produced by blocks 16g..16g+15
__device__ unsigned int g_cnt[8];

// ---------------- packed f32x2 helpers (Blackwell FFMA2 path) ----------------
__device__ __forceinline__ void ffma2(ull& d, ull a, ull b) {
    asm("fma.rn.f32x2 %0, %1, %2, %0;" : "+l"(d) : "l"(a), "l"(b));
}
__device__ __forceinline__ ull addf2(ull a, ull b) {
    ull r; asm("add.rn.f32x2 %0, %1, %2;" : "=l"(r) : "l"(a), "l"(b)); return r;
}
__device__ __forceinline__ ull pk2(float x, float y) {
    ull r; asm("mov.b64 %0, {%1, %2};" : "=l"(r) : "f"(x), "f"(y)); return r;
}
__device__ __forceinline__ float2 upk(ull v) {
    float2 r; asm("mov.b64 {%0, %1}, %2;" : "=f"(r.x), "=f"(r.y) : "l"(v)); return r;
}

// ---------------------------------------------------------------------------
// convert_split: pack x and w_ih into (hi|lo) bf16-split u32 arrays
// ---------------------------------------------------------------------------
__device__ __forceinline__ u32 pack_split(float x) {
    __nv_bfloat16 h = __float2bfloat16(x);
    float r = x - __bfloat162float(h);
    __nv_bfloat16 l = __float2bfloat16(r);
    return (u32)__bfloat16_as_ushort(h) | ((u32)__bfloat16_as_ushort(l) << 16);
}

__global__ void convert_split(const float* __restrict__ X, const float* __restrict__ W)
{
    const long long n4x = 33554432LL / 4;
    const long long n4w = 1048576LL / 4;
    long long i = (long long)blockIdx.x * blockDim.x + threadIdx.x;
    const float4* src;
    uint4* dst;
    long long j;
    if (i < n4x)            { src = (const float4*)X; dst = (uint4*)g_xs; j = i; }
    else if (i < n4x + n4w) { src = (const float4*)W; dst = (uint4*)g_ws; j = i - n4x; }
    else return;
    float4 v = src[j];
    uint4 o;
    o.x = pack_split(v.x);
    o.y = pack_split(v.y);
    o.z = pack_split(v.z);
    o.w = pack_split(v.w);
    dst[j] = o;
}

// ---------------------------------------------------------------------------
// gemm_bf16x3: gx = x @ wih^T + bih + bhh via m16n8k16 bf16 MMA, 3-term split.
//   Epilogue writes DIRECTLY into the rec-friendly gxT layout.
// ---------------------------------------------------------------------------
#define GP 9   // smem row pitch in u32

#define MMA_BF16(C, A0, A1, A2, A3, B0, B1)                                    \
    asm volatile(                                                              \
        "mma.sync.aligned.m16n8k16.row.col.f32.bf16.bf16.f32 "                 \
        "{%0,%1,%2,%3},{%4,%5,%6,%7},{%8,%9},{%0,%1,%2,%3};"                   \
        : "+f"((C)[0]), "+f"((C)[1]), "+f"((C)[2]), "+f"((C)[3])               \
        : "r"(A0), "r"(A1), "r"(A2), "r"(A3), "r"(B0), "r"(B1))

__global__ void __launch_bounds__(256, 2) gemm_bf16x3(
    const float* __restrict__ bih,
    const float* __restrict__ bhh)
{
    __shared__ u32 smem[2 * 4 * 128 * GP];

    const int tid = threadIdx.x;
    const int bm  = blockIdx.y * 128;
    const int bn  = blockIdx.x * 128;
    const int wid = tid >> 5;
    const int ln  = tid & 31;
    const int mw  = (wid >> 2) * 64;
    const int nw  = (wid & 3) * 32;
    const int lc  = ln & 3;
    const int lr4 = ln >> 2;

    const int lrow  = tid >> 1;
    const int lhalf = tid & 1;
    const u32* Ag = g_xs + (size_t)(bm + lrow) * 512 + lhalf * 8;
    const u32* Bg = g_ws + (size_t)(bn + lrow) * 512 + lhalf * 8;

    float acc[4][4][4];
#pragma unroll
    for (int mt = 0; mt < 4; mt++)
#pragma unroll
        for (int nt = 0; nt < 4; nt++)
#pragma unroll
            for (int q = 0; q < 4; q++) acc[mt][nt][q] = 0.f;

    float2 bias2[4];
#pragma unroll
    for (int nt = 0; nt < 4; nt++) {
        int c0 = bn + nw + nt * 8 + lc * 2;
        bias2[nt].x = bih[c0]     + bhh[c0];
        bias2[nt].y = bih[c0 + 1] + bhh[c0 + 1];
    }

    const int sts_base = lrow * GP + lhalf * 4;

    uint4 pa0 = *(const uint4*)(Ag);
    uint4 pa1 = *(const uint4*)(Ag + 4);
    uint4 pb0 = *(const uint4*)(Bg);
    uint4 pb1 = *(const uint4*)(Bg + 4);
    {
        u32* Ah = smem;               u32* Al = smem + 1152;
        u32* Bh = smem + 2304;        u32* Bl = smem + 3456;
        Ah[sts_base + 0] = __byte_perm(pa0.x, pa0.y, 0x5410);
        Ah[sts_base + 1] = __byte_perm(pa0.z, pa0.w, 0x5410);
        Ah[sts_base + 2] = __byte_perm(pa1.x, pa1.y, 0x5410);
        Ah[sts_base + 3] = __byte_perm(pa1.z, pa1.w, 0x5410);
        Al[sts_base + 0] = __byte_perm(pa0.x, pa0.y, 0x7632);
        Al[sts_base + 1] = __byte_perm(pa0.z, pa0.w, 0x7632);
        Al[sts_base + 2] = __byte_perm(pa1.x, pa1.y, 0x7632);
        Al[sts_base + 3] = __byte_perm(pa1.z, pa1.w, 0x7632);
        Bh[sts_base + 0] = __byte_perm(pb0.x, pb0.y, 0x5410);
        Bh[sts_base + 1] = __byte_perm(pb0.z, pb0.w, 0x5410);
        Bh[sts_base + 2] = __byte_perm(pb1.x, pb1.y, 0x5410);
        Bh[sts_base + 3] = __byte_perm(pb1.z, pb1.w, 0x5410);
        Bl[sts_base + 0] = __byte_perm(pb0.x, pb0.y, 0x7632);
        Bl[sts_base + 1] = __byte_perm(pb0.z, pb0.w, 0x7632);
        Bl[sts_base + 2] = __byte_perm(pb1.x, pb1.y, 0x7632);
        Bl[sts_base + 3] = __byte_perm(pb1.z, pb1.w, 0x7632);
    }
    __syncthreads();

    for (int s = 0; s < 32; s++) {
        if (s + 1 < 32) {
            pa0 = *(const uint4*)(Ag + (s + 1) * 16);
            pa1 = *(const uint4*)(Ag + (s + 1) * 16 + 4);
            pb0 = *(const uint4*)(Bg + (s + 1) * 16);
            pb1 = *(const uint4*)(Bg + (s + 1) * 16 + 4);
        }

        const u32* base = smem + (s & 1) * 4608;
        const u32* Ahi = base;
        const u32* Alo = base + 1152;
        const u32* Bhi = base + 2304;
        const u32* Blo = base + 3456;

        u32 bh[4][2], bl[4][2];
#pragma unroll
        for (int nt = 0; nt < 4; nt++) {
            int r = (nw + nt * 8 + lr4) * GP + lc;
            bh[nt][0] = Bhi[r];     bh[nt][1] = Bhi[r + 4];
            bl[nt][0] = Blo[r];     bl[nt][1] = Blo[r + 4];
        }

#pragma unroll
        for (int mt = 0; mt < 4; mt++) {
            int r0 = (mw + mt * 16 + lr4) * GP + lc;
            int r1 = r0 + 8 * GP;
            u32 ah0 = Ahi[r0], ah1 = Ahi[r1], ah2 = Ahi[r0 + 4], ah3 = Ahi[r1 + 4];
            u32 al0 = Alo[r0], al1 = Alo[r1], al2 = Alo[r0 + 4], al3 = Alo[r1 + 4];
#pragma unroll
            for (int nt = 0; nt < 4; nt++) {
                MMA_BF16(acc[mt][nt], ah0, ah1, ah2, ah3, bh[nt][0], bh[nt][1]);
                MMA_BF16(acc[mt][nt], ah0, ah1, ah2, ah3, bl[nt][0], bl[nt][1]);
                MMA_BF16(acc[mt][nt], al0, al1, al2, al3, bh[nt][0], bh[nt][1]);
            }
        }

        if (s + 1 < 32) {
            u32* nb = smem + ((s + 1) & 1) * 4608;
            u32* Ah = nb;          u32* Al = nb + 1152;
            u32* Bh = nb + 2304;   u32* Bl = nb + 3456;
            Ah[sts_base + 0] = __byte_perm(pa0.x, pa0.y, 0x5410);
            Ah[sts_base + 1] = __byte_perm(pa0.z, pa0.w, 0x5410);
            Ah[sts_base + 2] = __byte_perm(pa1.x, pa1.y, 0x5410);
            Ah[sts_base + 3] = __byte_perm(pa1.z, pa1.w, 0x5410);
            Al[sts_base + 0] = __byte_perm(pa0.x, pa0.y, 0x7632);
            Al[sts_base + 1] = __byte_perm(pa0.z, pa0.w, 0x7632);
            Al[sts_base + 2] = __byte_perm(pa1.x, pa1.y, 0x7632);
            Al[sts_base + 3] = __byte_perm(pa1.z, pa1.w, 0x7632);
            Bh[sts_base + 0] = __byte_perm(pb0.x, pb0.y, 0x5410);
            Bh[sts_base + 1] = __byte_perm(pb0.z, pb0.w, 0x5410);
            Bh[sts_base + 2] = __byte_perm(pb1.x, pb1.y, 0x5410);
            Bh[sts_base + 3] = __byte_perm(pb1.z, pb1.w, 0x5410);
            Bl[sts_base + 0] = __byte_perm(pb0.x, pb0.y, 0x7632);
            Bl[sts_base + 1] = __byte_perm(pb0.z, pb0.w, 0x7632);
            Bl[sts_base + 2] = __byte_perm(pb1.x, pb1.y, 0x7632);
            Bl[sts_base + 3] = __byte_perm(pb1.z, pb1.w, 0x7632);
            __syncthreads();
        }
    }

    // epilogue: write DIRECTLY into gxT[t][g][ublk][uu][b]
    //   row grow = t*32 + b ; col gcol = g*512 + u ; u = ublk*4 + uu
#pragma unroll
    for (int mt = 0; mt < 4; mt++) {
        int grow0 = bm + mw + mt * 16 + lr4;
#pragma unroll
        for (int nt = 0; nt < 4; nt++) {
            int gcol = bn + nw + nt * 8 + lc * 2;
            const int g    = gcol >> 9;
            const int u    = gcol & 511;
            const int ublk = u >> 2;
            const int uu   = u & 3;
            float v[2][2] = { { acc[mt][nt][0] + bias2[nt].x,
                                acc[mt][nt][1] + bias2[nt].y },
                              { acc[mt][nt][2] + bias2[nt].x,
                                acc[mt][nt][3] + bias2[nt].y } };
#pragma unroll
            for (int rr = 0; rr < 2; rr++) {
                const int grow = grow0 + rr * 8;
                const int t    = grow >> 5;
                const int b    = grow & 31;
                const size_t base = ((size_t)(t * 4 + g) * 128 + ublk) * 128 + b;
                g_gxT[base + uu * 32]       = v[rr][0];
                g_gxT[base + (uu + 1) * 32] = v[rr][1];
            }
        }
    }
}

// ---------------------------------------------------------------------------
// init: reset chunk flags + transpose h0 into g_ht[1][u][b]  (step 0 reads buf 1)
// ---------------------------------------------------------------------------
__global__ void init_rec(const float* __restrict__ h0)
{
    int i = blockIdx.x * 256 + threadIdx.x;   // 0..16383
    if (i < 8) g_cnt[i] = 0u;
    int b = i >> 9;
    int u = i & 511;
    g_ht[1][u * BATCH + b] = h0[i];
}

// ---------------------------------------------------------------------------
// Kernel 2: persistent recurrence — R13 core + line-coalesced gx prefetch
//   (4 x 128B lines per epi warp from gxT) + out stores bounced through smem.
// ---------------------------------------------------------------------------
#define RBLK 128
#define RTHR 256
// smem floats: WT[512*16]=8192 | RED[8*576]=4608 | CS[128] | HOUT[128]
#define SMEM_FLOATS (8192 + 4608 + 128 + 128)

__global__ void __launch_bounds__(RTHR, 1) lstm_rec(
    const float* __restrict__ c0,
    const float* __restrict__ whh,
    float* __restrict__ out, float* __restrict__ hn, float* __restrict__ cn)
{
    extern __shared__ float sm[];
    float* WT   = sm;             // [k:512][c:16]
    float* RED  = sm + 8192;      // [ks:8][b*18 + c]
    float* CS   = RED + 4608;     // [bb*4+uu]
    float* HOUT = CS + 128;       // [b:32][uu:4]

    const int tid = threadIdx.x;
    const int u0  = blockIdx.x * 4;
    const int my_chunk = blockIdx.x >> 4;

    // load w_hh slice: local col c = uu*4+gate <-> global row gate*512 + u0+uu
    for (int idx = tid; idx < 8192; idx += RTHR) {
        int c    = idx & 15;
        int k    = idx >> 4;
        int uu   = c >> 2;
        int gate = c & 3;
        int grow = gate * HID + u0 + uu;
        WT[idx] = whh[(size_t)grow * HID + k];
    }
    if (tid < 128) {
        int bb = tid >> 2, uu = tid & 3;
        CS[bb * 4 + uu] = c0[bb * HID + u0 + uu];
    }
    __syncthreads();

    const int ks  = tid >> 5;          // 0..7  (also = chunk this warp consumes)
    const int ln  = tid & 31;
    const int bq  = ln & 7;            // batches 4bq..4bq+3
    const int cq  = ln >> 3;           // cols 4cq..4cq+3
    const int ebb = tid & 31;          // epilogue batch
    const int euu = tid >> 5;          // epilogue unit (tid<128)

    // gxT address base for this epi thread: [t][g][ublk=bid][uu=euu][b=ebb]
    const size_t gx_off = (size_t)blockIdx.x * 128 + euu * 32 + ebb;

    // gx prefetch for t=0 (4 line-coalesced scalar loads per warp)
    float gxv[4];
    if (tid < 128) {
#pragma unroll
        for (int g = 0; g < 4; g++)
            gxv[g] = g_gxT[(size_t)g * 16384 + gx_off];
    }

    for (int t = 0; t < T_STEPS; t++) {
        const int rb = (t & 1) ^ 1;    // read buffer (h_{t-1})
        const int wb = t & 1;          // write buffer (h_t)

        // per-warp chunk wait: h_{t-1} rows 64ks.. ready when g_cnt[ks] >= 16*t
        if (t > 0) {
            if (ln == 0) {
                const unsigned tgt = 16u * (unsigned)t;
                unsigned v;
                do {
                    asm volatile("ld.acquire.gpu.global.u32 %0, [%1];"
                                 : "=r"(v) : "l"(&g_cnt[ks]) : "memory");
                } while (v < tgt);
            }
            __syncwarp();
        }

        // 4x4 microtile GEMM; h rows direct from L2 (fresh via ldcg)
        ull acc2[4][2];
#pragma unroll
        for (int i = 0; i < 4; i++) { acc2[i][0] = 0ull; acc2[i][1] = 0ull; }

        const float4* hp = (const float4*)(g_ht[rb] + (ks * 64) * BATCH + bq * 4);
        const float*  wp = WT + (ks * 64) * 16 + cq * 4;
#pragma unroll 16
        for (int k = 0; k < 64; k++) {
            float4 hv = __ldcg(hp); hp += 8;           // +32 floats (one row)
            ulonglong2 wq = *(const ulonglong2*)wp; wp += 16;
            ull h0d = pk2(hv.x, hv.x);
            ull h1d = pk2(hv.y, hv.y);
            ull h2d = pk2(hv.z, hv.z);
            ull h3d = pk2(hv.w, hv.w);
            ffma2(acc2[0][0], h0d, wq.x); ffma2(acc2[0][1], h0d, wq.y);
            ffma2(acc2[1][0], h1d, wq.x); ffma2(acc2[1][1], h1d, wq.y);
            ffma2(acc2[2][0], h2d, wq.x); ffma2(acc2[2][1], h2d, wq.y);
            ffma2(acc2[3][0], h3d, wq.x); ffma2(acc2[3][1], h3d, wq.y);
        }
        // write partials: RED[ks][b:32][c:16 pad 18]
        {
            float* rbuf = RED + ks * 576;
#pragma unroll
            for (int bb = 0; bb < 4; bb++) {
                ull* rp = (ull*)(rbuf + (4 * bq + bb) * 18 + 4 * cq);
                rp[0] = acc2[bb][0];
                rp[1] = acc2[bb][1];
            }
        }
        __syncthreads();   // RED ready; warps 4..7 fall through to next poll

        if (tid < 128) {
            const ull* q = (const ull*)(RED + ebb * 18 + euu * 4);
            ull s01 = 0ull, s23 = 0ull;
#pragma unroll
            for (int kq = 0; kq < 8; kq++) {
                s01 = addf2(s01, q[0]);
                s23 = addf2(s23, q[1]);
                q += 288;   // 576 floats
            }
            float2 p01 = upk(s01);
            float2 p23 = upk(s23);
            float iv = p01.x + gxv[0];
            float fv = p01.y + gxv[1];
            float gv = p23.x + gxv[2];
            float ov = p23.y + gxv[3];
            float it = 1.f / (1.f + __expf(-iv));
            float ft = 1.f / (1.f + __expf(-fv));
            float gt = tanhf(gv);
            float ot = 1.f / (1.f + __expf(-ov));
            float cc  = CS[ebb * 4 + euu];
            float cnv = ft * cc + it * gt;
            CS[ebb * 4 + euu] = cnv;
            float hv = ot * tanhf(cnv);

            // publish h_t + stage for coalesced out-store, then release ASAP
            g_ht[wb][(u0 + euu) * BATCH + ebb] = hv;
            HOUT[ebb * 4 + euu] = hv;
            asm volatile("bar.sync 1, 128;" ::: "memory");
            if (tid == 0 && t < T_STEPS - 1) {
                asm volatile("red.release.gpu.global.add.u32 [%0], 1;"
                             :: "l"(&g_cnt[my_chunk]) : "memory");
            }

            // off-critical-path: coalesced out store (32 x STG.128)
            if (tid < 32)
                *(float4*)&out[(size_t)t * BATCH * HID + tid * HID + u0] =
                    *(const float4*)&HOUT[tid * 4];

            // line-coalesced gx prefetch for t+1
            if (t + 1 < T_STEPS) {
                const size_t tb = (size_t)(t + 1) * 65536 + gx_off;
#pragma unroll
                for (int g = 0; g < 4; g++)
                    gxv[g] = g_gxT[tb + (size_t)g * 16384];
            } else {
                hn[ebb * HID + (u0 + euu)] = hv;
                cn[ebb * HID + (u0 + euu)] = cnv;
            }
        }
        // warps 4..7 loop straight to the next chunk wait (RED WAR safe via wait)
    }
}

// ---------------------------------------------------------------------------
extern "C" void kernel_launch(void* const* d_in, const int* in_sizes, int n_in,
                              void* d_out, int out_size)
{
    const float* x   = (const float*)d_in[0];
    const float* h0  = (const float*)d_in[1];
    const float* c0  = (const float*)d_in[2];
    const float* wih = (const float*)d_in[3];
    const float* bih = (const float*)d_in[4];
    const float* whh = (const float*)d_in[5];
    const float* bhh = (const float*)d_in[6];

    float* out = (float*)d_out;
    float* hn  = out + (size_t)T_STEPS * BATCH * HID;
    float* cn  = hn + BATCH * HID;

    init_rec<<<64, 256>>>(h0);
    convert_split<<<33792, 256>>>(x, wih);
    gemm_bf16x3<<<dim3(GATES / 128, (T_STEPS * BATCH) / 128), 256>>>(bih, bhh);

    const size_t shmem = SMEM_FLOATS * sizeof(float);
    cudaFuncSetAttribute(lstm_rec, cudaFuncAttributeMaxDynamicSharedMemorySize, (int)shmem);
    lstm_rec<<<RBLK, RTHR, shmem>>>(c0, whh, out, hn, cn);
}

// round 17
// speedup vs baseline: 1.1318x; 1.0087x over previous
#include <cuda_runtime.h>
#include <cuda_bf16.h>
#include <cstdint>
#include <cstddef>

#define T_STEPS 2048
#define BATCH   32
#define DIM     512
#define HID     512
#define GATES   2048   // 4*HID

typedef unsigned long long ull;
typedef unsigned int u32;

// gx in rec-friendly layout: [t][g:4][ublk:128][uu:4][b:32]
__device__ float g_gxT[134217728];

// bf16-split packed inputs: u32 = (hi bf16) | (lo bf16 << 16)
__device__ __align__(16) u32 g_xs[33554432];   // x   [65536, 512]
__device__ __align__(16) u32 g_ws[1048576];    // wih [2048, 512]

// double-buffered transposed hidden state h_T[buf][u][b]
__device__ __align__(16) float g_ht[2][HID * BATCH];

// per-chunk monotonic flags: chunk g = h rows [64g, 64g+64), produced by blocks 16g..16g+15
__device__ unsigned int g_cnt[8];

// ---------------- packed f32x2 helpers (Blackwell FFMA2 path) ----------------
__device__ __forceinline__ void ffma2(ull& d, ull a, ull b) {
    asm("fma.rn.f32x2 %0, %1, %2, %0;" : "+l"(d) : "l"(a), "l"(b));
}
__device__ __forceinline__ ull addf2(ull a, ull b) {
    ull r; asm("add.rn.f32x2 %0, %1, %2;" : "=l"(r) : "l"(a), "l"(b)); return r;
}
__device__ __forceinline__ ull pk2(float x, float y) {
    ull r; asm("mov.b64 %0, {%1, %2};" : "=l"(r) : "f"(x), "f"(y)); return r;
}
__device__ __forceinline__ float2 upk(ull v) {
    float2 r; asm("mov.b64 {%0, %1}, %2;" : "=f"(r.x), "=f"(r.y) : "l"(v)); return r;
}

// fast gate math (MUFU paths; saturation-safe)
__device__ __forceinline__ float sigm_f(float x) {
    return __fdividef(1.f, 1.f + __expf(-x));
}
__device__ __forceinline__ float tanh_f(float x) {
    float e = __expf(2.f * x);
    return 1.f - __fdividef(2.f, e + 1.f);
}

// ---------------------------------------------------------------------------
// convert_split: pack x and w_ih into (hi|lo) bf16-split u32 arrays
// ---------------------------------------------------------------------------
__device__ __forceinline__ u32 pack_split(float x) {
    __nv_bfloat16 h = __float2bfloat16(x);
    float r = x - __bfloat162float(h);
    __nv_bfloat16 l = __float2bfloat16(r);
    return (u32)__bfloat16_as_ushort(h) | ((u32)__bfloat16_as_ushort(l) << 16);
}

__global__ void convert_split(const float* __restrict__ X, const float* __restrict__ W)
{
    const long long n4x = 33554432LL / 4;
    const long long n4w = 1048576LL / 4;
    long long i = (long long)blockIdx.x * blockDim.x + threadIdx.x;
    const float4* src;
    uint4* dst;
    long long j;
    if (i < n4x)            { src = (const float4*)X; dst = (uint4*)g_xs; j = i; }
    else if (i < n4x + n4w) { src = (const float4*)W; dst = (uint4*)g_ws; j = i - n4x; }
    else return;
    float4 v = src[j];
    uint4 o;
    o.x = pack_split(v.x);
    o.y = pack_split(v.y);
    o.z = pack_split(v.z);
    o.w = pack_split(v.w);
    dst[j] = o;
}

// ---------------------------------------------------------------------------
// gemm_bf16x3: gx = x @ wih^T + bih + bhh via m16n8k16 bf16 MMA, 3-term split.
//   Epilogue: smem-staged transpose -> fully coalesced gxT stores.
// ---------------------------------------------------------------------------
#define GP 9     // smem row pitch in u32 (MMA stage)
#define SP 130   // epilogue stage pitch in floats (even: aligned f2; odd/2: low conflicts)

#define MMA_BF16(C, A0, A1, A2, A3, B0, B1)                                    \
    asm volatile(                                                              \
        "mma.sync.aligned.m16n8k16.row.col.f32.bf16.bf16.f32 "                 \
        "{%0,%1,%2,%3},{%4,%5,%6,%7},{%8,%9},{%0,%1,%2,%3};"                   \
        : "+f"((C)[0]), "+f"((C)[1]), "+f"((C)[2]), "+f"((C)[3])               \
        : "r"(A0), "r"(A1), "r"(A2), "r"(A3), "r"(B0), "r"(B1))

__global__ void __launch_bounds__(256, 2) gemm_bf16x3(
    const float* __restrict__ bih,
    const float* __restrict__ bhh)
{
    __shared__ u32 smem[2 * 4 * 128 * GP];   // 9216 u32 = 36 KB (also reused as stage)

    const int tid = threadIdx.x;
    const int bm  = blockIdx.y * 128;
    const int bn  = blockIdx.x * 128;
    const int wid = tid >> 5;
    const int ln  = tid & 31;
    const int mw  = (wid >> 2) * 64;
    const int nw  = (wid & 3) * 32;
    const int lc  = ln & 3;
    const int lr4 = ln >> 2;

    const int lrow  = tid >> 1;
    const int lhalf = tid & 1;
    const u32* Ag = g_xs + (size_t)(bm + lrow) * 512 + lhalf * 8;
    const u32* Bg = g_ws + (size_t)(bn + lrow) * 512 + lhalf * 8;

    float acc[4][4][4];
#pragma unroll
    for (int mt = 0; mt < 4; mt++)
#pragma unroll
        for (int nt = 0; nt < 4; nt++)
#pragma unroll
            for (int q = 0; q < 4; q++) acc[mt][nt][q] = 0.f;

    float2 bias2[4];
#pragma unroll
    for (int nt = 0; nt < 4; nt++) {
        int c0 = bn + nw + nt * 8 + lc * 2;
        bias2[nt].x = bih[c0]     + bhh[c0];
        bias2[nt].y = bih[c0 + 1] + bhh[c0 + 1];
    }

    const int sts_base = lrow * GP + lhalf * 4;

    uint4 pa0 = *(const uint4*)(Ag);
    uint4 pa1 = *(const uint4*)(Ag + 4);
    uint4 pb0 = *(const uint4*)(Bg);
    uint4 pb1 = *(const uint4*)(Bg + 4);
    {
        u32* Ah = smem;               u32* Al = smem + 1152;
        u32* Bh = smem + 2304;        u32* Bl = smem + 3456;
        Ah[sts_base + 0] = __byte_perm(pa0.x, pa0.y, 0x5410);
        Ah[sts_base + 1] = __byte_perm(pa0.z, pa0.w, 0x5410);
        Ah[sts_base + 2] = __byte_perm(pa1.x, pa1.y, 0x5410);
        Ah[sts_base + 3] = __byte_perm(pa1.z, pa1.w, 0x5410);
        Al[sts_base + 0] = __byte_perm(pa0.x, pa0.y, 0x7632);
        Al[sts_base + 1] = __byte_perm(pa0.z, pa0.w, 0x7632);
        Al[sts_base + 2] = __byte_perm(pa1.x, pa1.y, 0x7632);
        Al[sts_base + 3] = __byte_perm(pa1.z, pa1.w, 0x7632);
        Bh[sts_base + 0] = __byte_perm(pb0.x, pb0.y, 0x5410);
        Bh[sts_base + 1] = __byte_perm(pb0.z, pb0.w, 0x5410);
        Bh[sts_base + 2] = __byte_perm(pb1.x, pb1.y, 0x5410);
        Bh[sts_base + 3] = __byte_perm(pb1.z, pb1.w, 0x5410);
        Bl[sts_base + 0] = __byte_perm(pb0.x, pb0.y, 0x7632);
        Bl[sts_base + 1] = __byte_perm(pb0.z, pb0.w, 0x7632);
        Bl[sts_base + 2] = __byte_perm(pb1.x, pb1.y, 0x7632);
        Bl[sts_base + 3] = __byte_perm(pb1.z, pb1.w, 0x7632);
    }
    __syncthreads();

    for (int s = 0; s < 32; s++) {
        if (s + 1 < 32) {
            pa0 = *(const uint4*)(Ag + (s + 1) * 16);
            pa1 = *(const uint4*)(Ag + (s + 1) * 16 + 4);
            pb0 = *(const uint4*)(Bg + (s + 1) * 16);
            pb1 = *(const uint4*)(Bg + (s + 1) * 16 + 4);
        }

        const u32* base = smem + (s & 1) * 4608;
        const u32* Ahi = base;
        const u32* Alo = base + 1152;
        const u32* Bhi = base + 2304;
        const u32* Blo = base + 3456;

        u32 bh[4][2], bl[4][2];
#pragma unroll
        for (int nt = 0; nt < 4; nt++) {
            int r = (nw + nt * 8 + lr4) * GP + lc;
            bh[nt][0] = Bhi[r];     bh[nt][1] = Bhi[r + 4];
            bl[nt][0] = Blo[r];     bl[nt][1] = Blo[r + 4];
        }

#pragma unroll
        for (int mt = 0; mt < 4; mt++) {
            int r0 = (mw + mt * 16 + lr4) * GP + lc;
            int r1 = r0 + 8 * GP;
            u32 ah0 = Ahi[r0], ah1 = Ahi[r1], ah2 = Ahi[r0 + 4], ah3 = Ahi[r1 + 4];
            u32 al0 = Alo[r0], al1 = Alo[r1], al2 = Alo[r0 + 4], al3 = Alo[r1 + 4];
#pragma unroll
            for (int nt = 0; nt < 4; nt++) {
                MMA_BF16(acc[mt][nt], ah0, ah1, ah2, ah3, bh[nt][0], bh[nt][1]);
                MMA_BF16(acc[mt][nt], ah0, ah1, ah2, ah3, bl[nt][0], bl[nt][1]);
                MMA_BF16(acc[mt][nt], al0, al1, al2, al3, bh[nt][0], bh[nt][1]);
            }
        }

        if (s + 1 < 32) {
            u32* nb = smem + ((s + 1) & 1) * 4608;
            u32* Ah = nb;          u32* Al = nb + 1152;
            u32* Bh = nb + 2304;   u32* Bl = nb + 3456;
            Ah[sts_base + 0] = __byte_perm(pa0.x, pa0.y, 0x5410);
            Ah[sts_base + 1] = __byte_perm(pa0.z, pa0.w, 0x5410);
            Ah[sts_base + 2] = __byte_perm(pa1.x, pa1.y, 0x5410);
            Ah[sts_base + 3] = __byte_perm(pa1.z, pa1.w, 0x5410);
            Al[sts_base + 0] = __byte_perm(pa0.x, pa0.y, 0x7632);
            Al[sts_base + 1] = __byte_perm(pa0.z, pa0.w, 0x7632);
            Al[sts_base + 2] = __byte_perm(pa1.x, pa1.y, 0x7632);
            Al[sts_base + 3] = __byte_perm(pa1.z, pa1.w, 0x7632);
            Bh[sts_base + 0] = __byte_perm(pb0.x, pb0.y, 0x5410);
            Bh[sts_base + 1] = __byte_perm(pb0.z, pb0.w, 0x5410);
            Bh[sts_base + 2] = __byte_perm(pb1.x, pb1.y, 0x5410);
            Bh[sts_base + 3] = __byte_perm(pb1.z, pb1.w, 0x5410);
            Bl[sts_base + 0] = __byte_perm(pb0.x, pb0.y, 0x7632);
            Bl[sts_base + 1] = __byte_perm(pb0.z, pb0.w, 0x7632);
            Bl[sts_base + 2] = __byte_perm(pb1.x, pb1.y, 0x7632);
            Bl[sts_base + 3] = __byte_perm(pb1.z, pb1.w, 0x7632);
            __syncthreads();
        }
    }
    __syncthreads();   // MMA stage smem now free for the epilogue stage

    // epilogue: smem-staged transpose into gxT[t][g][ublk][uu][b], coalesced.
    // tile never crosses a g boundary (bn multiple of 128).
    float* stage = (float*)smem;                // [64][SP]
    const int g     = bn >> 9;
    const int ublk0 = (bn & 511) >> 2;
    const int t0    = bm >> 5;                  // multiple of 4

#pragma unroll
    for (int h = 0; h < 2; h++) {
        if (mw == h * 64) {
#pragma unroll
            for (int mt = 0; mt < 4; mt++) {
                int r0 = mt * 16 + lr4;         // within-half row
#pragma unroll
                for (int nt = 0; nt < 4; nt++) {
                    int col = nw + nt * 8 + lc * 2;
                    float2 v0 = { acc[mt][nt][0] + bias2[nt].x,
                                  acc[mt][nt][1] + bias2[nt].y };
                    float2 v1 = { acc[mt][nt][2] + bias2[nt].x,
                                  acc[mt][nt][3] + bias2[nt].y };
                    *(float2*)&stage[r0 * SP + col]       = v0;
                    *(float2*)&stage[(r0 + 8) * SP + col] = v1;
                }
            }
        }
        __syncthreads();

        // 2048 float4 vectors: v = ((tt*32 + j)*4 + uu)*8 + b4
#pragma unroll
        for (int it = 0; it < 8; it++) {
            int v  = tid + it * 256;
            int tt = v >> 10;
            int j  = (v >> 5) & 31;
            int uu = (v >> 3) & 3;
            int b  = (v & 7) * 4;
            int col = j * 4 + uu;
            float4 o;
            o.x = stage[(tt * 32 + b + 0) * SP + col];
            o.y = stage[(tt * 32 + b + 1) * SP + col];
            o.z = stage[(tt * 32 + b + 2) * SP + col];
            o.w = stage[(tt * 32 + b + 3) * SP + col];
            const int t = t0 + h * 2 + tt;
            const size_t base = ((size_t)(t * 4 + g) * 128 + ublk0) * 128;
            *(float4*)&g_gxT[base + j * 128 + uu * 32 + b] = o;
        }
        __syncthreads();
    }
}

// ---------------------------------------------------------------------------
// init: reset chunk flags + transpose h0 into g_ht[1][u][b]  (step 0 reads buf 1)
// ---------------------------------------------------------------------------
__global__ void init_rec(const float* __restrict__ h0)
{
    int i = blockIdx.x * 256 + threadIdx.x;   // 0..16383
    if (i < 8) g_cnt[i] = 0u;
    int b = i >> 9;
    int u = i & 511;
    g_ht[1][u * BATCH + b] = h0[i];
}

// ---------------------------------------------------------------------------
// Kernel 2: persistent recurrence — R16 core + fast gate math.
// ---------------------------------------------------------------------------
#define RBLK 128
#define RTHR 256
// smem floats: WT[512*16]=8192 | RED[8*576]=4608 | CS[128] | HOUT[128]
#define SMEM_FLOATS (8192 + 4608 + 128 + 128)

__global__ void __launch_bounds__(RTHR, 1) lstm_rec(
    const float* __restrict__ c0,
    const float* __restrict__ whh,
    float* __restrict__ out, float* __restrict__ hn, float* __restrict__ cn)
{
    extern __shared__ float sm[];
    float* WT   = sm;             // [k:512][c:16]
    float* RED  = sm + 8192;      // [ks:8][b*18 + c]
    float* CS   = RED + 4608;     // [bb*4+uu]
    float* HOUT = CS + 128;       // [b:32][uu:4]

    const int tid = threadIdx.x;
    const int u0  = blockIdx.x * 4;
    const int my_chunk = blockIdx.x >> 4;

    // load w_hh slice: local col c = uu*4+gate <-> global row gate*512 + u0+uu
    for (int idx = tid; idx < 8192; idx += RTHR) {
        int c    = idx & 15;
        int k    = idx >> 4;
        int uu   = c >> 2;
        int gate = c & 3;
        int grow = gate * HID + u0 + uu;
        WT[idx] = whh[(size_t)grow * HID + k];
    }
    if (tid < 128) {
        int bb = tid >> 2, uu = tid & 3;
        CS[bb * 4 + uu] = c0[bb * HID + u0 + uu];
    }
    __syncthreads();

    const int ks  = tid >> 5;          // 0..7  (also = chunk this warp consumes)
    const int ln  = tid & 31;
    const int bq  = ln & 7;            // batches 4bq..4bq+3
    const int cq  = ln >> 3;           // cols 4cq..4cq+3
    const int ebb = tid & 31;          // epilogue batch
    const int euu = tid >> 5;          // epilogue unit (tid<128)

    // gxT address base for this epi thread: [t][g][ublk=bid][uu=euu][b=ebb]
    const size_t gx_off = (size_t)blockIdx.x * 128 + euu * 32 + ebb;

    // gx prefetch for t=0 (4 line-coalesced scalar loads per warp)
    float gxv[4];
    if (tid < 128) {
#pragma unroll
        for (int g = 0; g < 4; g++)
            gxv[g] = g_gxT[(size_t)g * 16384 + gx_off];
    }

    for (int t = 0; t < T_STEPS; t++) {
        const int rb = (t & 1) ^ 1;    // read buffer (h_{t-1})
        const int wb = t & 1;          // write buffer (h_t)

        // per-warp chunk wait: h_{t-1} rows 64ks.. ready when g_cnt[ks] >= 16*t
        if (t > 0) {
            if (ln == 0) {
                const unsigned tgt = 16u * (unsigned)t;
                unsigned v;
                do {
                    asm volatile("ld.acquire.gpu.global.u32 %0, [%1];"
                                 : "=r"(v) : "l"(&g_cnt[ks]) : "memory");
                } while (v < tgt);
            }
            __syncwarp();
        }

        // 4x4 microtile GEMM; h rows direct from L2 (fresh via ldcg)
        ull acc2[4][2];
#pragma unroll
        for (int i = 0; i < 4; i++) { acc2[i][0] = 0ull; acc2[i][1] = 0ull; }

        const float4* hp = (const float4*)(g_ht[rb] + (ks * 64) * BATCH + bq * 4);
        const float*  wp = WT + (ks * 64) * 16 + cq * 4;
#pragma unroll 16
        for (int k = 0; k < 64; k++) {
            float4 hv = __ldcg(hp); hp += 8;           // +32 floats (one row)
            ulonglong2 wq = *(const ulonglong2*)wp; wp += 16;
            ull h0d = pk2(hv.x, hv.x);
            ull h1d = pk2(hv.y, hv.y);
            ull h2d = pk2(hv.z, hv.z);
            ull h3d = pk2(hv.w, hv.w);
            ffma2(acc2[0][0], h0d, wq.x); ffma2(acc2[0][1], h0d, wq.y);
            ffma2(acc2[1][0], h1d, wq.x); ffma2(acc2[1][1], h1d, wq.y);
            ffma2(acc2[2][0], h2d, wq.x); ffma2(acc2[2][1], h2d, wq.y);
            ffma2(acc2[3][0], h3d, wq.x); ffma2(acc2[3][1], h3d, wq.y);
        }
        // write partials: RED[ks][b:32][c:16 pad 18]
        {
            float* rbuf = RED + ks * 576;
#pragma unroll
            for (int bb = 0; bb < 4; bb++) {
                ull* rp = (ull*)(rbuf + (4 * bq + bb) * 18 + 4 * cq);
                rp[0] = acc2[bb][0];
                rp[1] = acc2[bb][1];
            }
        }
        __syncthreads();   // RED ready; warps 4..7 fall through to next poll

        if (tid < 128) {
            const ull* q = (const ull*)(RED + ebb * 18 + euu * 4);
            ull s01 = 0ull, s23 = 0ull;
#pragma unroll
            for (int kq = 0; kq < 8; kq++) {
                s01 = addf2(s01, q[0]);
                s23 = addf2(s23, q[1]);
                q += 288;   // 576 floats
            }
            float2 p01 = upk(s01);
            float2 p23 = upk(s23);
            float iv = p01.x + gxv[0];
            float fv = p01.y + gxv[1];
            float gv = p23.x + gxv[2];
            float ov = p23.y + gxv[3];
            float it = sigm_f(iv);
            float ft = sigm_f(fv);
            float gt = tanh_f(gv);
            float ot = sigm_f(ov);
            float cc  = CS[ebb * 4 + euu];
            float cnv = ft * cc + it * gt;
            CS[ebb * 4 + euu] = cnv;
            float hv = ot * tanh_f(cnv);

            // publish h_t + stage for coalesced out-store, then release ASAP
            g_ht[wb][(u0 + euu) * BATCH + ebb] = hv;
            HOUT[ebb * 4 + euu] = hv;
            asm volatile("bar.sync 1, 128;" ::: "memory");
            if (tid == 0 && t < T_STEPS - 1) {
                asm volatile("red.release.gpu.global.add.u32 [%0], 1;"
                             :: "l"(&g_cnt[my_chunk]) : "memory");
            }

            // off-critical-path: coalesced out store (32 x STG.128)
            if (tid < 32)
                *(float4*)&out[(size_t)t * BATCH * HID + tid * HID + u0] =
                    *(const float4*)&HOUT[tid * 4];

            // line-coalesced gx prefetch for t+1
            if (t + 1 < T_STEPS) {
                const size_t tb = (size_t)(t + 1) * 65536 + gx_off;
#pragma unroll
                for (int g = 0; g < 4; g++)
                    gxv[g] = g_gxT[tb + (size_t)g * 16384];
            } else {
                hn[ebb * HID + (u0 + euu)] = hv;
                cn[ebb * HID + (u0 + euu)] = cnv;
            }
        }
        // warps 4..7 loop straight to the next chunk wait (RED WAR safe via wait)
    }
}

// ---------------------------------------------------------------------------
extern "C" void kernel_launch(void* const* d_in, const int* in_sizes, int n_in,
                              void* d_out, int out_size)
{
    const float* x   = (const float*)d_in[0];
    const float* h0  = (const float*)d_in[1];
    const float* c0  = (const float*)d_in[2];
    const float* wih = (const float*)d_in[3];
    const float* bih = (const float*)d_in[4];
    const float* whh = (const float*)d_in[5];
    const float* bhh = (const float*)d_in[6];

    float* out = (float*)d_out;
    float* hn  = out + (size_t)T_STEPS * BATCH * HID;
    float* cn  = hn + BATCH * HID;

    init_rec<<<64, 256>>>(h0);
    convert_split<<<33792, 256>>>(x, wih);
    gemm_bf16x3<<<dim3(GATES / 128, (T_STEPS * BATCH) / 128), 256>>>(bih, bhh);

    const size_t shmem = SMEM_FLOATS * sizeof(float);
    cudaFuncSetAttribute(lstm_rec, cudaFuncAttributeMaxDynamicSharedMemorySize, (int)shmem);
    lstm_rec<<<RBLK, RTHR, shmem>>>(c0, whh, out, hn, cn);
}